// round 5
// baseline (speedup 1.0000x reference)
#include <cuda_runtime.h>
#include <cuda_bf16.h>
#include <cstdint>

// Problem shape (fixed by the reference)
#define BB 8
#define CC 16
#define HH 512
#define WW 1024

// One thread handles 2 consecutive-w pixels of one (b,h) row.
// disp is shared across the 16 channels: compute x0/x1/weights once per pixel,
// then loop channels (unroll 4 -> 8 gather loads batched in flight).
// Per channel iter: 4 gather loads + one aligned float2 store.
// __launch_bounds__(256, 6) caps regs at ~42 -> 48 warps/SM (75% occ) to hide
// DRAM latency; round-4 profile showed occ=45.6% was the limiter (DRAM 68%).
__global__ __launch_bounds__(256, 6) void warp_disp_kernel(
    const float* __restrict__ input,   // [B,C,H,W]
    const float* __restrict__ disp,    // [B,1,H,W]
    float* __restrict__ out)           // [B,C,H,W]
{
    const int tid = blockIdx.x * blockDim.x + threadIdx.x;   // 2M threads
    const int w0  = (tid * 2) & (WW - 1);                    // 0..1022, step 2
    const int bh  = tid / (WW / 2);                          // b*H + h
    const int h   = bh & (HH - 1);
    const int b   = bh >> 9;                                 // /HH

    // disp layout [B,1,H,W] == [B*H*W]; aligned float2 load
    const float2 d2 = *(const float2*)(disp + bh * WW + w0);

    int   x0[2], x1[2];
    float wl[2], wr[2];
    const float dvals[2] = {d2.x, d2.y};
    #pragma unroll
    for (int i = 0; i < 2; ++i) {
        float x = (float)(w0 + i) + dvals[i];
        x = fminf(fmaxf(x, 0.0f), (float)(WW - 1));
        const float x0f = floorf(x);
        const float x1f = fminf(x0f + 1.0f, (float)(WW - 1));
        x0[i] = (int)x0f;
        x1[i] = (int)x1f;
        wl[i] = x1f - x;          // note: NOT 1-wr; both 0 at the right clamp
        wr[i] = x - x0f;
    }

    // All element offsets fit in int32 (max 64M elements).
    const int row_base = (b * CC * HH + h) * WW;
    const float* in_row = input + row_base;
    float*      out_row = out   + row_base + w0;
    const int cstride = HH * WW;   // 524288

    #pragma unroll 4
    for (int c = 0; c < CC; ++c) {
        const float* rc = in_row + c * cstride;
        float2 r;
        r.x = wl[0] * __ldg(rc + x0[0]) + wr[0] * __ldg(rc + x1[0]);
        r.y = wl[1] * __ldg(rc + x0[1]) + wr[1] * __ldg(rc + x1[1]);
        *(float2*)(out_row + c * cstride) = r;
    }
}

extern "C" void kernel_launch(void* const* d_in, const int* in_sizes, int n_in,
                              void* d_out, int out_size) {
    const float* input = (const float*)d_in[0];
    const float* disp  = (const float*)d_in[1];
    float* out = (float*)d_out;

    const int n_threads = BB * HH * (WW / 2);   // 2,097,152
    const int threads = 256;
    warp_disp_kernel<<<n_threads / threads, threads>>>(input, disp, out);
}